// round 14
// baseline (speedup 1.0000x reference)
#include <cuda_runtime.h>
#include <cuda_fp16.h>
#include <math.h>
#include <cstdint>

#define BATCH 128
#define NPT   500
#define NROWS (BATCH*NPT)

typedef unsigned long long ull;

// ---------------- scratch (static; no allocation) ----------------
__device__ __align__(256) __half g_actP[52428800];
__device__ __align__(256) __half g_actQ[52428800];
__device__ __align__(256) __half g_wH[742528];
__device__ __align__(256) __half g_tailX[NROWS * 8];   // [x.xyz fp16, 0 x5] natural order
__device__ __align__(256) int g_idx1[BATCH * 500];
__device__ __align__(256) int g_idx2[BATCH * 1000];
__device__ __align__(256) unsigned g_mask[2048];       // 64000-bit idx2 membership bitmap

// weight arena offsets (elements, K padded to mult of 8)
#define OFF_W2   0
#define OFF_PC1  16384
#define OFF_W3   81920
#define OFF_W4   149504
#define OFF_PC2  247808
#define OFF_W5   395264
#define OFF_W6   545792

// ---------------- helpers ----------------
__device__ __forceinline__ uint32_t smem_u32(const void* p) {
    uint32_t a;
    asm("{ .reg .u64 t; cvta.to.shared.u64 t, %1; cvt.u32.u64 %0, t; }" : "=r"(a) : "l"(p));
    return a;
}
__device__ __forceinline__ void cpa16(uint32_t dst, const void* src, int sz) {
    asm volatile("cp.async.cg.shared.global [%0], [%1], 16, %2;"
        :: "r"(dst), "l"(src), "r"(sz) : "memory");
}
__device__ __forceinline__ void ldm_x4(uint32_t* r, uint32_t addr) {
    asm volatile("ldmatrix.sync.aligned.m8n8.x4.shared.b16 {%0,%1,%2,%3}, [%4];"
        : "=r"(r[0]), "=r"(r[1]), "=r"(r[2]), "=r"(r[3]) : "r"(addr));
}
__device__ __forceinline__ void mma_f16(float* d, const uint32_t* a, uint32_t b0, uint32_t b1) {
    asm volatile("mma.sync.aligned.m16n8k16.row.col.f32.f16.f16.f32 "
        "{%0,%1,%2,%3}, {%4,%5,%6,%7}, {%8,%9}, {%0,%1,%2,%3};"
        : "+f"(d[0]), "+f"(d[1]), "+f"(d[2]), "+f"(d[3])
        : "r"(a[0]), "r"(a[1]), "r"(a[2]), "r"(a[3]), "r"(b0), "r"(b1));
}

// ---------------- fp16 HMMA GEMM: CTA 256x128x64, 8 warps 4Mx2N, warp tile 64x64 ----------
// C = relu?( sum_k A[m,k]*W[n,k] + bias[n] ). 3-stage cp.async, stage = A 32K | W 16K = 48KB.
// 1 CTA/SM (smem). rowIdx: absolute A rows (smem-cached). tailA: K cols >= lda, by OUTPUT row.
// mode: 0 fp32 C, 1 fp16 C, 2 fused masked per-500-row-batch column max into Cf.
#define NSTG 3
#define STG 49152
static const int GEMM_SMEM = NSTG * STG + 1024;

__device__ __forceinline__ void g_fill(
    const __half* __restrict__ A, const __half* __restrict__ W,
    const int* __restrict__ sIdx, int useIdx, const __half* __restrict__ tailA,
    int K, int lda, int row0, int col0, int s, int nst, uint32_t sb, int tid)
{
    if (s < nst) {
        int k0 = s << 6;
        uint32_t base = sb + (uint32_t)(s % NSTG) * STG;
#pragma unroll
        for (int i = 0; i < 8; i++) {              // A: 256 rows x 8 chunks
            int g = (i << 8) + tid;
            int r = g >> 3, c = g & 7;
            int kg = k0 + (c << 3);
            int ok = (kg < K) ? 16 : 0;
            uint32_t d = base + ((uint32_t)r << 7) + (((uint32_t)(c ^ (r & 7))) << 4);
            int srcRow = useIdx ? sIdx[r] : (row0 + r);
            const __half* srcA;
            if (tailA != nullptr && kg >= lda)
                srcA = tailA + (size_t)(row0 + r) * 8 + (kg - lda);
            else
                srcA = A + (size_t)srcRow * lda + kg;
            cpa16(d, srcA, ok);
        }
#pragma unroll
        for (int i = 0; i < 4; i++) {              // W: 128 rows x 8 chunks
            int g = (i << 8) + tid;
            int r = g >> 3, c = g & 7;
            int kg = k0 + (c << 3);
            int ok = (kg < K) ? 16 : 0;
            uint32_t d = base + 32768 + ((uint32_t)r << 7) + (((uint32_t)(c ^ (r & 7))) << 4);
            cpa16(d, W + (size_t)(col0 + r) * K + kg, ok);
        }
    }
    asm volatile("cp.async.commit_group;" ::: "memory");
}

__global__ void __launch_bounds__(256, 1)
gemm_f16(const __half* __restrict__ A, const __half* __restrict__ W,
         const float* __restrict__ bias,
         float* __restrict__ Cf, __half* __restrict__ Ch,
         const int* __restrict__ rowIdx, const __half* __restrict__ tailA,
         const unsigned* __restrict__ maskp,
         int M, int N, int K, int lda, int relu, int mode)
{
    extern __shared__ char smem[];
    int* sIdx = (int*)(smem + NSTG * STG);
    uint32_t sb = smem_u32(smem);
    int tid = threadIdx.x, lane = tid & 31, wid = tid >> 5;
    int warp_m = wid & 3;        // 4 M-warps, 64 rows each
    int warp_n = wid >> 2;       // 2 N-warps, 64 cols each
    int row0 = blockIdx.y << 8;
    int col0 = blockIdx.x << 7;
    int nst = (K + 63) >> 6;
    int useIdx = (rowIdx != nullptr);

    if (useIdx) sIdx[tid] = rowIdx[row0 + tid];
    __syncthreads();

    float acc[4][8][4];
#pragma unroll
    for (int a = 0; a < 4; a++)
#pragma unroll
        for (int b = 0; b < 8; b++)
#pragma unroll
            for (int c = 0; c < 4; c++) acc[a][b][c] = 0.f;

    g_fill(A, W, sIdx, useIdx, tailA, K, lda, row0, col0, 0, nst, sb, tid);
    g_fill(A, W, sIdx, useIdx, tailA, K, lda, row0, col0, 1, nst, sb, tid);

    int a_row = warp_m * 64 + (lane & 15);
    int a_sel = lane >> 4;
    int b_row4 = warp_n * 64 + ((lane >> 4) << 3) + (lane & 7);
    int b_ksel = (lane >> 3) & 1;

    for (int s = 0; s < nst; s++) {
        asm volatile("cp.async.wait_group 1;" ::: "memory");
        __syncthreads();
        uint32_t base = sb + (uint32_t)(s % NSTG) * STG;
        int kr = K - (s << 6);
        int kcnt = (kr + 15) >> 4; if (kcnt > 4) kcnt = 4;
        for (int ks = 0; ks < kcnt; ks++) {
            uint32_t Fa[4][4];
            int ch_a = (ks << 1) + a_sel;
#pragma unroll
            for (int mi = 0; mi < 4; mi++) {
                int rr = a_row + mi * 16;
                ldm_x4(Fa[mi], base + ((uint32_t)rr << 7) + (((uint32_t)(ch_a ^ (rr & 7))) << 4));
            }
            int ch_b = (ks << 1) + b_ksel;
#pragma unroll
            for (int np = 0; np < 4; np++) {
                int nr = b_row4 + np * 16;
                uint32_t B4[4];
                ldm_x4(B4, base + 32768 + ((uint32_t)nr << 7)
                           + (((uint32_t)(ch_b ^ (nr & 7))) << 4));
#pragma unroll
                for (int mi = 0; mi < 4; mi++) {
                    mma_f16(acc[mi][np * 2],     Fa[mi], B4[0], B4[1]);
                    mma_f16(acc[mi][np * 2 + 1], Fa[mi], B4[2], B4[3]);
                }
            }
        }
        g_fill(A, W, sIdx, useIdx, tailA, K, lda, row0, col0, s + 2, nst, sb, tid);
    }

    int er = row0 + warp_m * 64 + (lane >> 2);
    int ec = col0 + warp_n * 64 + ((lane & 3) << 1);
    if (mode != 2) {
#pragma unroll
        for (int ni = 0; ni < 8; ni++) {
            int c = ec + ni * 8;
            float b0 = __ldg(bias + c), b1 = __ldg(bias + c + 1);
#pragma unroll
            for (int mi = 0; mi < 4; mi++) {
                int r = er + mi * 16;
                float v00 = acc[mi][ni][0] + b0, v01 = acc[mi][ni][1] + b1;
                float v10 = acc[mi][ni][2] + b0, v11 = acc[mi][ni][3] + b1;
                if (relu) {
                    v00 = fmaxf(v00, 0.f); v01 = fmaxf(v01, 0.f);
                    v10 = fmaxf(v10, 0.f); v11 = fmaxf(v11, 0.f);
                }
                if (mode == 0) {
                    *(float2*)(Cf + (size_t)r * N + c)       = make_float2(v00, v01);
                    *(float2*)(Cf + (size_t)(r + 8) * N + c) = make_float2(v10, v11);
                } else {
                    *(__half2*)(Ch + (size_t)r * N + c)       = __floats2half2_rn(v00, v01);
                    *(__half2*)(Ch + (size_t)(r + 8) * N + c) = __floats2half2_rn(v10, v11);
                }
            }
        }
    } else {
        // masked per-batch (500 rows) column max -> Cf[batch][N] via atomicMax (values >= 0).
        // 256-row tile straddles at most one batch boundary (500 > 256).
        int bat0 = row0 / 500;
        int cut = (bat0 + 1) * 500;
        bool has2 = (row0 + 255 >= cut);
        int* outI = (int*)Cf;
        float inc[8];
#pragma unroll
        for (int mi = 0; mi < 4; mi++) {
            int ra = er + mi * 16, rb = ra + 8;
            inc[mi * 2]     = ((maskp[ra >> 5] >> (ra & 31)) & 1u) ? 1.f : 0.f;
            inc[mi * 2 + 1] = ((maskp[rb >> 5] >> (rb & 31)) & 1u) ? 1.f : 0.f;
        }
#pragma unroll
        for (int ni = 0; ni < 8; ni++) {
            int c = ec + ni * 8;
            float b0 = __ldg(bias + c), b1 = __ldg(bias + c + 1);
            float s00 = 0.f, s01 = 0.f, s10 = 0.f, s11 = 0.f;
#pragma unroll
            for (int mi = 0; mi < 4; mi++) {
                int r = er + mi * 16;
                float v00 = fmaxf(acc[mi][ni][0] + b0, 0.f) * inc[mi * 2];
                float v01 = fmaxf(acc[mi][ni][1] + b1, 0.f) * inc[mi * 2];
                float v10 = fmaxf(acc[mi][ni][2] + b0, 0.f) * inc[mi * 2 + 1];
                float v11 = fmaxf(acc[mi][ni][3] + b1, 0.f) * inc[mi * 2 + 1];
                if (r < cut)     { s00 = fmaxf(s00, v00); s01 = fmaxf(s01, v01); }
                else             { s10 = fmaxf(s10, v00); s11 = fmaxf(s11, v01); }
                if (r + 8 < cut) { s00 = fmaxf(s00, v10); s01 = fmaxf(s01, v11); }
                else             { s10 = fmaxf(s10, v10); s11 = fmaxf(s11, v11); }
            }
#pragma unroll
            for (int d = 4; d <= 16; d <<= 1) {
                s00 = fmaxf(s00, __shfl_xor_sync(0xffffffffu, s00, d));
                s01 = fmaxf(s01, __shfl_xor_sync(0xffffffffu, s01, d));
                s10 = fmaxf(s10, __shfl_xor_sync(0xffffffffu, s10, d));
                s11 = fmaxf(s11, __shfl_xor_sync(0xffffffffu, s11, d));
            }
            if ((lane >> 2) == 0) {
                atomicMax(outI + bat0 * N + c,     __float_as_int(s00));
                atomicMax(outI + bat0 * N + c + 1, __float_as_int(s01));
                if (has2) {
                    atomicMax(outI + (bat0 + 1) * N + c,     __float_as_int(s10));
                    atomicMax(outI + (bat0 + 1) * N + c + 1, __float_as_int(s11));
                }
            }
        }
    }
}

// ---------------- out init ----------------
__global__ void init_out(float* __restrict__ out) {
    int t = blockIdx.x * 256 + threadIdx.x;
    if (t < BATCH * 512) out[t] = 0.f;
}

// ---------------- mask init + build ----------------
__global__ void init_mask() {
    int t = blockIdx.x * 256 + threadIdx.x;
    if (t < 2048) g_mask[t] = 0u;
}
__global__ void build_mask(const int* __restrict__ idx2) {
    int t = blockIdx.x * 256 + threadIdx.x;
    if (t >= BATCH * 1000) return;
    int v = idx2[t];
    atomicOr(&g_mask[v >> 5], 1u << (v & 31));
}

// ---------------- weight pack (fp32 -> fp16, pad K) ----------------
__global__ void pack_w(const float* __restrict__ w2, const float* __restrict__ pc1,
                       const float* __restrict__ w3, const float* __restrict__ w4,
                       const float* __restrict__ pc2, const float* __restrict__ w5,
                       const float* __restrict__ w6) {
    int t = blockIdx.x * 256 + threadIdx.x;
    if (t >= 742400) return;
    float v;
    if (t < 81920) {
        v = (t < 16384) ? w2[t] : pc1[t - 16384];
    } else if (t < 149504) {
        int i = t - 81920; int r = i / 264, c = i - r * 264;
        v = (c < 259) ? w3[r * 259 + c] : 0.f;
    } else if (t < 247808) {
        v = w4[t - 149504];
    } else if (t < 395264) {
        v = pc2[t - 247808];
    } else if (t < 545792) {
        int i = t - 395264; int r = i / 392, c = i - r * 392;
        v = (c < 387) ? w5[r * 387 + c] : 0.f;
    } else {
        v = w6[t - 545792];
    }
    g_wH[t] = __float2half_rn(v);
}

// ---------------- fused conf + concat + first linear + x-tail -> fp16 ----------------
__global__ void point_mlp1(const float* __restrict__ x,
                           const float* __restrict__ confW, const float* __restrict__ confb,
                           const float* __restrict__ w1, const float* __restrict__ b1) {
    int t = blockIdx.x * 256 + threadIdx.x;
    if (t >= NROWS * 4) return;
    int p = t >> 2, g = t & 3;
    float x0 = x[p * 3], x1 = x[p * 3 + 1], x2 = x[p * 3 + 2];
    float s = confW[0] * x0 + confW[1] * x1 + confW[2] * x2 + confb[0];
    float conf = 1.f / (1.f + expf(-s));
    const float* wr = w1 + (g * 16) * 4;
    __half h[16];
#pragma unroll
    for (int r = 0; r < 16; r++) {
        float a = __ldg(b1 + g * 16 + r)
                + __ldg(wr + r * 4 + 0) * conf + __ldg(wr + r * 4 + 1) * x0
                + __ldg(wr + r * 4 + 2) * x1   + __ldg(wr + r * 4 + 3) * x2;
        h[r] = __float2half_rn(fmaxf(a, 0.f));
    }
    size_t o = (size_t)p * 64 + g * 16;
    *(uint4*)(g_actP + o)     = *(uint4*)h;
    *(uint4*)(g_actP + o + 8) = *(uint4*)(h + 8);
    if (g == 0) {
        __half tx[8];
#pragma unroll
        for (int j = 0; j < 8; j++) tx[j] = __float2half(0.f);
        tx[0] = __float2half_rn(x0); tx[1] = __float2half_rn(x1); tx[2] = __float2half_rn(x2);
        *(uint4*)(g_tailX + (size_t)p * 8) = *(uint4*)tx;
    }
}

// ---------------- FPS: 4 warps/batch, exact XLA arithmetic, provable early-exit -------------
__global__ void fps_run(const float* __restrict__ x, const int* __restrict__ far0,
                        int* __restrict__ idxout, int npoint) {
    __shared__ float sxx[512], sxy[512], sxz[512];
    __shared__ unsigned cmb[4][2], cix[4][2];
    int b = blockIdx.x;
    int* out = idxout + b * npoint;
    int abs0 = b * NPT;
    int far = far0[b];
    const float* xb = x + (size_t)b * NPT * 3;
    int tid = threadIdx.x;
    int w = tid >> 5;

    float px[4], py[4], pz[4], dist[4];
#pragma unroll
    for (int j = 0; j < 4; j++) {
        int p = j * 128 + tid;
        if (p < NPT) {
            px[j] = xb[p * 3]; py[j] = xb[p * 3 + 1]; pz[j] = xb[p * 3 + 2];
            dist[j] = 1e10f;
            sxx[p] = px[j]; sxy[p] = py[j]; sxz[p] = pz[j];
        } else {
            px[j] = 0.f; py[j] = 0.f; pz[j] = 0.f;
            dist[j] = -1.0f;
        }
    }
    __syncthreads();

    for (int t = 0; t < npoint; t++) {
        if (tid == 0) out[t] = abs0 + far;
        if (t + 1 == npoint) break;
        float cx = sxx[far], cy = sxy[far], cz = sxz[far];
        float nd[4];
#pragma unroll
        for (int j = 0; j < 4; j++) {
            float dx = __fsub_rn(px[j], cx);
            float dy = __fsub_rn(py[j], cy);
            float dz = __fsub_rn(pz[j], cz);
            float d  = __fadd_rn(__fadd_rn(__fmul_rn(dx, dx), __fmul_rn(dy, dy)),
                                 __fmul_rn(dz, dz));
            nd[j] = fminf(dist[j], d);
            dist[j] = nd[j];
        }
        float m0 = fmaxf(nd[0], nd[1]), m1 = fmaxf(nd[2], nd[3]);
        float best = fmaxf(m0, m1);
        unsigned mb = __reduce_max_sync(0xffffffffu, __float_as_uint(best));
        unsigned c[4];
#pragma unroll
        for (int j = 0; j < 4; j++)
            c[j] = (__float_as_uint(nd[j]) == mb) ? (unsigned)(j * 128 + tid) : 0xffffffffu;
        unsigned cw = __reduce_min_sync(0xffffffffu, min(min(c[0], c[1]), min(c[2], c[3])));
        int sl = t & 1;
        if ((tid & 31) == 0) { cmb[w][sl] = mb; cix[w][sl] = cw; }
        __syncthreads();
        unsigned q0 = cmb[0][sl], q1 = cmb[1][sl], q2 = cmb[2][sl], q3 = cmb[3][sl];
        unsigned fm = max(max(q0, q1), max(q2, q3));
        unsigned i0 = (q0 == fm) ? cix[0][sl] : 0xffffffffu;
        unsigned i1 = (q1 == fm) ? cix[1][sl] : 0xffffffffu;
        unsigned i2 = (q2 == fm) ? cix[2][sl] : 0xffffffffu;
        unsigned i3 = (q3 == fm) ? cix[3][sl] : 0xffffffffu;
        far = (int)min(min(i0, i1), min(i2, i3));
        if (fm == 0u) {
            for (int q = t + 1 + tid; q < npoint; q += 128) out[q] = abs0;
            break;
        }
    }
}

// ---------------- launch ----------------
extern "C" void kernel_launch(void* const* d_in, const int* in_sizes, int n_in,
                              void* d_out, int out_size) {
    const float* x     = (const float*)d_in[0];
    const float* confW = (const float*)d_in[1];
    const float* confb = (const float*)d_in[2];
    const float* w1    = (const float*)d_in[3];
    const float* b1    = (const float*)d_in[4];
    const float* w2    = (const float*)d_in[5];
    const float* b2    = (const float*)d_in[6];
    const float* pc1W  = (const float*)d_in[7];
    const float* pc1b  = (const float*)d_in[8];
    const float* w3    = (const float*)d_in[9];
    const float* b3    = (const float*)d_in[10];
    const float* w4    = (const float*)d_in[11];
    const float* b4    = (const float*)d_in[12];
    const float* pc2W  = (const float*)d_in[13];
    const float* pc2b  = (const float*)d_in[14];
    const float* w5    = (const float*)d_in[15];
    const float* b5    = (const float*)d_in[16];
    const float* w6    = (const float*)d_in[17];
    const float* b6    = (const float*)d_in[18];
    const int* far1    = (const int*)d_in[20];
    const int* far2    = (const int*)d_in[21];
    float* out = (float*)d_out;

    __half *actP, *actQ, *wH, *tailX;
    int *idx1, *idx2;
    unsigned* maskp;
    cudaGetSymbolAddress((void**)&actP, g_actP);
    cudaGetSymbolAddress((void**)&actQ, g_actQ);
    cudaGetSymbolAddress((void**)&wH,   g_wH);
    cudaGetSymbolAddress((void**)&tailX, g_tailX);
    cudaGetSymbolAddress((void**)&idx1, g_idx1);
    cudaGetSymbolAddress((void**)&idx2, g_idx2);
    cudaGetSymbolAddress((void**)&maskp, g_mask);

    cudaFuncSetAttribute(gemm_f16, cudaFuncAttributeMaxDynamicSharedMemorySize, GEMM_SMEM);

    static cudaStream_t s1 = nullptr, s2 = nullptr;
    static cudaEvent_t evA = nullptr, ev1 = nullptr, ev2 = nullptr, evW = nullptr;
    if (s1 == nullptr) {
        cudaStreamCreateWithFlags(&s1, cudaStreamNonBlocking);
        cudaStreamCreateWithFlags(&s2, cudaStreamNonBlocking);
        cudaEventCreateWithFlags(&evA, cudaEventDisableTiming);
        cudaEventCreateWithFlags(&ev1, cudaEventDisableTiming);
        cudaEventCreateWithFlags(&ev2, cudaEventDisableTiming);
        cudaEventCreateWithFlags(&evW, cudaEventDisableTiming);
    }

    // fork: s1 = init_out + FPS1 ; s2 = init_mask + pack_w + FPS2 + mask
    cudaEventRecord(evA, 0);
    cudaStreamWaitEvent(s1, evA, 0);
    cudaStreamWaitEvent(s2, evA, 0);
    init_out<<<(BATCH * 512 + 255) / 256, 256, 0, s1>>>(out);
    fps_run<<<BATCH, 128, 0, s1>>>(x, far1, idx1, 500);
    cudaEventRecord(ev1, s1);
    init_mask<<<8, 256, 0, s2>>>();
    pack_w<<<(742400 + 255) / 256, 256, 0, s2>>>(w2, pc1W, w3, w4, pc2W, w5, w6);
    cudaEventRecord(evW, s2);
    fps_run<<<BATCH, 128, 0, s2>>>(x, far2, idx2, 1000);
    build_mask<<<(BATCH * 1000 + 255) / 256, 256, 0, s2>>>(idx2);
    cudaEventRecord(ev2, s2);

    // main stream: mlp1 (+tail fused), then GEMM chain (waits for weights)
    point_mlp1<<<(NROWS * 4 + 255) / 256, 256>>>(x, confW, confb, w1, b1);
    cudaStreamWaitEvent(0, evW, 0);

    // l2: (64000x256, K=64), relu        actP -> actQ
    gemm_f16<<<dim3(2, 250), 256, GEMM_SMEM>>>(actP, wH + OFF_W2, b2,
        nullptr, actQ, nullptr, nullptr, nullptr, NROWS, 256, 64, 64, 1, 1);
    // l3: (64000x256, K=256)             actQ -> actP
    gemm_f16<<<dim3(2, 250), 256, GEMM_SMEM>>>(actQ, wH + OFF_PC1, pc1b,
        nullptr, actP, nullptr, nullptr, nullptr, NROWS, 256, 256, 256, 0, 1);
    // l4' (natural order): A = l3 + x-tail, K=264, relu   actP -> actQ
    gemm_f16<<<dim3(2, 250), 256, GEMM_SMEM>>>(actP, wH + OFF_W3, b3,
        nullptr, actQ, nullptr, tailX, nullptr, NROWS, 256, 264, 256, 1, 1);
    // l5': (64000x384, K=256), relu      actQ -> actP
    gemm_f16<<<dim3(3, 250), 256, GEMM_SMEM>>>(actQ, wH + OFF_W4, b4,
        nullptr, actP, nullptr, nullptr, nullptr, NROWS, 384, 256, 256, 1, 1);
    // l6': (64000x384, K=384)            actP -> actQ
    gemm_f16<<<dim3(3, 250), 256, GEMM_SMEM>>>(actP, wH + OFF_PC2, pc2b,
        nullptr, actQ, nullptr, nullptr, nullptr, NROWS, 384, 384, 384, 0, 1);

    // join idx1; l7 over positions: A row j = l6'[idx1[j]], tail = x[j]
    cudaStreamWaitEvent(0, ev1, 0);
    gemm_f16<<<dim3(3, 250), 256, GEMM_SMEM>>>(actQ, wH + OFF_W5, b5,
        nullptr, actP, idx1, tailX, nullptr, NROWS, 384, 392, 384, 1, 1);

    // join idx2 bitmap; l8 masked fused max-pool -> out
    cudaStreamWaitEvent(0, ev2, 0);
    gemm_f16<<<dim3(4, 250), 256, GEMM_SMEM>>>(actP, wH + OFF_W6, b6,
        out, nullptr, nullptr, nullptr, maskp, NROWS, 512, 384, 384, 1, 2);
}

// round 15
// speedup vs baseline: 1.0183x; 1.0183x over previous
#include <cuda_runtime.h>
#include <cuda_fp16.h>
#include <math.h>
#include <cstdint>

#define BATCH 128
#define NPT   500
#define NROWS (BATCH*NPT)

typedef unsigned long long ull;

// ---------------- scratch (static; no allocation) ----------------
__device__ __align__(256) __half g_actP[52428800];
__device__ __align__(256) __half g_actQ[52428800];
__device__ __align__(256) __half g_wH[742528];
__device__ __align__(256) __half g_tailX[NROWS * 8];   // [x.xyz fp16, 0 x5] natural order
__device__ __align__(256) int g_idx1[BATCH * 500];
__device__ __align__(256) int g_idx2[BATCH * 1000];
__device__ __align__(256) unsigned g_mask[2048];       // 64000-bit idx2 membership bitmap

// weight arena offsets (elements, K padded to mult of 8)
#define OFF_W2   0
#define OFF_PC1  16384
#define OFF_W3   81920
#define OFF_W4   149504
#define OFF_PC2  247808
#define OFF_W5   395264
#define OFF_W6   545792

// ---------------- helpers ----------------
__device__ __forceinline__ uint32_t smem_u32(const void* p) {
    uint32_t a;
    asm("{ .reg .u64 t; cvta.to.shared.u64 t, %1; cvt.u32.u64 %0, t; }" : "=r"(a) : "l"(p));
    return a;
}
__device__ __forceinline__ void cpa16(uint32_t dst, const void* src, int sz) {
    asm volatile("cp.async.cg.shared.global [%0], [%1], 16, %2;"
        :: "r"(dst), "l"(src), "r"(sz) : "memory");
}
__device__ __forceinline__ void ldm_x4(uint32_t* r, uint32_t addr) {
    asm volatile("ldmatrix.sync.aligned.m8n8.x4.shared.b16 {%0,%1,%2,%3}, [%4];"
        : "=r"(r[0]), "=r"(r[1]), "=r"(r[2]), "=r"(r[3]) : "r"(addr));
}
__device__ __forceinline__ void mma_f16(float* d, const uint32_t* a, uint32_t b0, uint32_t b1) {
    asm volatile("mma.sync.aligned.m16n8k16.row.col.f32.f16.f16.f32 "
        "{%0,%1,%2,%3}, {%4,%5,%6,%7}, {%8,%9}, {%0,%1,%2,%3};"
        : "+f"(d[0]), "+f"(d[1]), "+f"(d[2]), "+f"(d[3])
        : "r"(a[0]), "r"(a[1]), "r"(a[2]), "r"(a[3]), "r"(b0), "r"(b1));
}

// ---------------- fp16 HMMA GEMM (R12-proven: CTA 128x128x64, 8 warps 2Mx4N, warp 64x32) ----
// C = relu?( sum_k A[m,k]*W[n,k] + bias[n] ). 3-stage cp.async (32KB/stage), 2 CTAs/SM.
// rowIdx: absolute A rows (smem-cached). tailA: K cols >= lda, indexed by OUTPUT row.
// mode: 0 fp32 C, 1 fp16 C, 2 fused masked per-500-row-batch column max into Cf.
#define NSTG 3
#define STG 32768
static const int GEMM_SMEM = NSTG * STG + 512;

__device__ __forceinline__ void g_fill(
    const __half* __restrict__ A, const __half* __restrict__ W,
    const int* __restrict__ sIdx, int useIdx, const __half* __restrict__ tailA,
    int K, int lda, int row0, int col0, int s, int nst, uint32_t sb, int tid)
{
    if (s < nst) {
        int k0 = s << 6;
        uint32_t base = sb + (uint32_t)(s % NSTG) * STG;
#pragma unroll
        for (int i = 0; i < 4; i++) {
            int g = (i << 8) + tid;
            int r = g >> 3, c = g & 7;
            int kg = k0 + (c << 3);
            int ok = (kg < K) ? 16 : 0;
            uint32_t d = base + ((uint32_t)r << 7) + (((uint32_t)(c ^ (r & 7))) << 4);
            int srcRow = useIdx ? sIdx[r] : (row0 + r);
            const __half* srcA;
            if (tailA != nullptr && kg >= lda)
                srcA = tailA + (size_t)(row0 + r) * 8 + (kg - lda);
            else
                srcA = A + (size_t)srcRow * lda + kg;
            cpa16(d,         srcA, ok);
            cpa16(d + 16384, W + (size_t)(col0 + r) * K + kg, ok);
        }
    }
    asm volatile("cp.async.commit_group;" ::: "memory");
}

__global__ void __launch_bounds__(256, 2)
gemm_f16(const __half* __restrict__ A, const __half* __restrict__ W,
         const float* __restrict__ bias,
         float* __restrict__ Cf, __half* __restrict__ Ch,
         const int* __restrict__ rowIdx, const __half* __restrict__ tailA,
         const unsigned* __restrict__ maskp,
         int M, int N, int K, int lda, int relu, int mode)
{
    extern __shared__ char smem[];
    int* sIdx = (int*)(smem + NSTG * STG);
    uint32_t sb = smem_u32(smem);
    int tid = threadIdx.x, lane = tid & 31, wid = tid >> 5;
    int warp_m = wid & 1;
    int warp_n = wid >> 1;
    int row0 = blockIdx.y << 7;
    int col0 = blockIdx.x << 7;
    int nst = (K + 63) >> 6;
    int useIdx = (rowIdx != nullptr);

    if (useIdx && tid < 128) sIdx[tid] = rowIdx[row0 + tid];
    __syncthreads();

    float acc[4][4][4];
#pragma unroll
    for (int a = 0; a < 4; a++)
#pragma unroll
        for (int b = 0; b < 4; b++)
#pragma unroll
            for (int c = 0; c < 4; c++) acc[a][b][c] = 0.f;

    g_fill(A, W, sIdx, useIdx, tailA, K, lda, row0, col0, 0, nst, sb, tid);
    g_fill(A, W, sIdx, useIdx, tailA, K, lda, row0, col0, 1, nst, sb, tid);

    int a_row = warp_m * 64 + (lane & 15);
    int a_sel = lane >> 4;
    int b_row4 = warp_n * 32 + ((lane >> 4) << 3) + (lane & 7);
    int b_ksel = (lane >> 3) & 1;

    for (int s = 0; s < nst; s++) {
        asm volatile("cp.async.wait_group 1;" ::: "memory");
        __syncthreads();
        uint32_t base = sb + (uint32_t)(s % NSTG) * STG;
        int kr = K - (s << 6);
        int kcnt = (kr + 15) >> 4; if (kcnt > 4) kcnt = 4;
        for (int ks = 0; ks < kcnt; ks++) {
            uint32_t Fa[4][4];
            int ch_a = (ks << 1) + a_sel;
#pragma unroll
            for (int mi = 0; mi < 4; mi++) {
                int rr = a_row + mi * 16;
                ldm_x4(Fa[mi], base + ((uint32_t)rr << 7) + (((uint32_t)(ch_a ^ (rr & 7))) << 4));
            }
            int ch_b = (ks << 1) + b_ksel;
#pragma unroll
            for (int np = 0; np < 2; np++) {
                int nr = b_row4 + np * 16;
                uint32_t B4[4];
                ldm_x4(B4, base + 16384 + ((uint32_t)nr << 7)
                           + (((uint32_t)(ch_b ^ (nr & 7))) << 4));
#pragma unroll
                for (int mi = 0; mi < 4; mi++) {
                    mma_f16(acc[mi][np * 2],     Fa[mi], B4[0], B4[1]);
                    mma_f16(acc[mi][np * 2 + 1], Fa[mi], B4[2], B4[3]);
                }
            }
        }
        g_fill(A, W, sIdx, useIdx, tailA, K, lda, row0, col0, s + 2, nst, sb, tid);
    }

    int er = row0 + warp_m * 64 + (lane >> 2);
    int ec = col0 + warp_n * 32 + ((lane & 3) << 1);
    if (mode != 2) {
#pragma unroll
        for (int ni = 0; ni < 4; ni++) {
            int c = ec + ni * 8;
            float b0 = __ldg(bias + c), b1 = __ldg(bias + c + 1);
#pragma unroll
            for (int mi = 0; mi < 4; mi++) {
                int r = er + mi * 16;
                float v00 = acc[mi][ni][0] + b0, v01 = acc[mi][ni][1] + b1;
                float v10 = acc[mi][ni][2] + b0, v11 = acc[mi][ni][3] + b1;
                if (relu) {
                    v00 = fmaxf(v00, 0.f); v01 = fmaxf(v01, 0.f);
                    v10 = fmaxf(v10, 0.f); v11 = fmaxf(v11, 0.f);
                }
                if (mode == 0) {
                    *(float2*)(Cf + (size_t)r * N + c)       = make_float2(v00, v01);
                    *(float2*)(Cf + (size_t)(r + 8) * N + c) = make_float2(v10, v11);
                } else {
                    *(__half2*)(Ch + (size_t)r * N + c)       = __floats2half2_rn(v00, v01);
                    *(__half2*)(Ch + (size_t)(r + 8) * N + c) = __floats2half2_rn(v10, v11);
                }
            }
        }
    } else {
        // masked per-batch (500 rows) column max -> Cf[batch][N] via atomicMax (values >= 0)
        int bat0 = row0 / 500;
        int cut = (bat0 + 1) * 500;
        bool has2 = (row0 + 127 >= cut);
        int* outI = (int*)Cf;
        float inc[8];
#pragma unroll
        for (int mi = 0; mi < 4; mi++) {
            int ra = er + mi * 16, rb = ra + 8;
            inc[mi * 2]     = ((maskp[ra >> 5] >> (ra & 31)) & 1u) ? 1.f : 0.f;
            inc[mi * 2 + 1] = ((maskp[rb >> 5] >> (rb & 31)) & 1u) ? 1.f : 0.f;
        }
#pragma unroll
        for (int ni = 0; ni < 4; ni++) {
            int c = ec + ni * 8;
            float b0 = __ldg(bias + c), b1 = __ldg(bias + c + 1);
            float s00 = 0.f, s01 = 0.f, s10 = 0.f, s11 = 0.f;
#pragma unroll
            for (int mi = 0; mi < 4; mi++) {
                int r = er + mi * 16;
                float v00 = fmaxf(acc[mi][ni][0] + b0, 0.f) * inc[mi * 2];
                float v01 = fmaxf(acc[mi][ni][1] + b1, 0.f) * inc[mi * 2];
                float v10 = fmaxf(acc[mi][ni][2] + b0, 0.f) * inc[mi * 2 + 1];
                float v11 = fmaxf(acc[mi][ni][3] + b1, 0.f) * inc[mi * 2 + 1];
                if (r < cut)     { s00 = fmaxf(s00, v00); s01 = fmaxf(s01, v01); }
                else             { s10 = fmaxf(s10, v00); s11 = fmaxf(s11, v01); }
                if (r + 8 < cut) { s00 = fmaxf(s00, v10); s01 = fmaxf(s01, v11); }
                else             { s10 = fmaxf(s10, v10); s11 = fmaxf(s11, v11); }
            }
#pragma unroll
            for (int d = 4; d <= 16; d <<= 1) {
                s00 = fmaxf(s00, __shfl_xor_sync(0xffffffffu, s00, d));
                s01 = fmaxf(s01, __shfl_xor_sync(0xffffffffu, s01, d));
                s10 = fmaxf(s10, __shfl_xor_sync(0xffffffffu, s10, d));
                s11 = fmaxf(s11, __shfl_xor_sync(0xffffffffu, s11, d));
            }
            if ((lane >> 2) == 0) {
                atomicMax(outI + bat0 * N + c,     __float_as_int(s00));
                atomicMax(outI + bat0 * N + c + 1, __float_as_int(s01));
                if (has2) {
                    atomicMax(outI + (bat0 + 1) * N + c,     __float_as_int(s10));
                    atomicMax(outI + (bat0 + 1) * N + c + 1, __float_as_int(s11));
                }
            }
        }
    }
}

// ---------------- out init ----------------
__global__ void init_out(float* __restrict__ out) {
    int t = blockIdx.x * 256 + threadIdx.x;
    if (t < BATCH * 512) out[t] = 0.f;
}

// ---------------- mask init + build ----------------
__global__ void init_mask() {
    int t = blockIdx.x * 256 + threadIdx.x;
    if (t < 2048) g_mask[t] = 0u;
}
__global__ void build_mask(const int* __restrict__ idx2) {
    int t = blockIdx.x * 256 + threadIdx.x;
    if (t >= BATCH * 1000) return;
    int v = idx2[t];
    atomicOr(&g_mask[v >> 5], 1u << (v & 31));
}

// ---------------- weight pack (fp32 -> fp16, pad K) ----------------
__global__ void pack_w(const float* __restrict__ w2, const float* __restrict__ pc1,
                       const float* __restrict__ w3, const float* __restrict__ w4,
                       const float* __restrict__ pc2, const float* __restrict__ w5,
                       const float* __restrict__ w6) {
    int t = blockIdx.x * 256 + threadIdx.x;
    if (t >= 742400) return;
    float v;
    if (t < 81920) {
        v = (t < 16384) ? w2[t] : pc1[t - 16384];
    } else if (t < 149504) {
        int i = t - 81920; int r = i / 264, c = i - r * 264;
        v = (c < 259) ? w3[r * 259 + c] : 0.f;
    } else if (t < 247808) {
        v = w4[t - 149504];
    } else if (t < 395264) {
        v = pc2[t - 247808];
    } else if (t < 545792) {
        int i = t - 395264; int r = i / 392, c = i - r * 392;
        v = (c < 387) ? w5[r * 387 + c] : 0.f;
    } else {
        v = w6[t - 545792];
    }
    g_wH[t] = __float2half_rn(v);
}

// ---------------- fused conf + concat + first linear + x-tail -> fp16 ----------------
__global__ void point_mlp1(const float* __restrict__ x,
                           const float* __restrict__ confW, const float* __restrict__ confb,
                           const float* __restrict__ w1, const float* __restrict__ b1) {
    int t = blockIdx.x * 256 + threadIdx.x;
    if (t >= NROWS * 4) return;
    int p = t >> 2, g = t & 3;
    float x0 = x[p * 3], x1 = x[p * 3 + 1], x2 = x[p * 3 + 2];
    float s = confW[0] * x0 + confW[1] * x1 + confW[2] * x2 + confb[0];
    float conf = 1.f / (1.f + expf(-s));
    const float* wr = w1 + (g * 16) * 4;
    __half h[16];
#pragma unroll
    for (int r = 0; r < 16; r++) {
        float a = __ldg(b1 + g * 16 + r)
                + __ldg(wr + r * 4 + 0) * conf + __ldg(wr + r * 4 + 1) * x0
                + __ldg(wr + r * 4 + 2) * x1   + __ldg(wr + r * 4 + 3) * x2;
        h[r] = __float2half_rn(fmaxf(a, 0.f));
    }
    size_t o = (size_t)p * 64 + g * 16;
    *(uint4*)(g_actP + o)     = *(uint4*)h;
    *(uint4*)(g_actP + o + 8) = *(uint4*)(h + 8);
    if (g == 0) {
        __half tx[8];
#pragma unroll
        for (int j = 0; j < 8; j++) tx[j] = __float2half(0.f);
        tx[0] = __float2half_rn(x0); tx[1] = __float2half_rn(x1); tx[2] = __float2half_rn(x2);
        *(uint4*)(g_tailX + (size_t)p * 8) = *(uint4*)tx;
    }
}

// ---------------- FPS: 4 warps/batch, exact XLA arithmetic, provable early-exit -------------
__global__ void fps_run(const float* __restrict__ x, const int* __restrict__ far0,
                        int* __restrict__ idxout, int npoint) {
    __shared__ float sxx[512], sxy[512], sxz[512];
    __shared__ unsigned cmb[4][2], cix[4][2];
    int b = blockIdx.x;
    int* out = idxout + b * npoint;
    int abs0 = b * NPT;
    int far = far0[b];
    const float* xb = x + (size_t)b * NPT * 3;
    int tid = threadIdx.x;
    int w = tid >> 5;

    float px[4], py[4], pz[4], dist[4];
#pragma unroll
    for (int j = 0; j < 4; j++) {
        int p = j * 128 + tid;
        if (p < NPT) {
            px[j] = xb[p * 3]; py[j] = xb[p * 3 + 1]; pz[j] = xb[p * 3 + 2];
            dist[j] = 1e10f;
            sxx[p] = px[j]; sxy[p] = py[j]; sxz[p] = pz[j];
        } else {
            px[j] = 0.f; py[j] = 0.f; pz[j] = 0.f;
            dist[j] = -1.0f;
        }
    }
    __syncthreads();

    for (int t = 0; t < npoint; t++) {
        if (tid == 0) out[t] = abs0 + far;
        if (t + 1 == npoint) break;
        float cx = sxx[far], cy = sxy[far], cz = sxz[far];
        float nd[4];
#pragma unroll
        for (int j = 0; j < 4; j++) {
            float dx = __fsub_rn(px[j], cx);
            float dy = __fsub_rn(py[j], cy);
            float dz = __fsub_rn(pz[j], cz);
            float d  = __fadd_rn(__fadd_rn(__fmul_rn(dx, dx), __fmul_rn(dy, dy)),
                                 __fmul_rn(dz, dz));
            nd[j] = fminf(dist[j], d);
            dist[j] = nd[j];
        }
        float m0 = fmaxf(nd[0], nd[1]), m1 = fmaxf(nd[2], nd[3]);
        float best = fmaxf(m0, m1);
        unsigned mb = __reduce_max_sync(0xffffffffu, __float_as_uint(best));
        unsigned c[4];
#pragma unroll
        for (int j = 0; j < 4; j++)
            c[j] = (__float_as_uint(nd[j]) == mb) ? (unsigned)(j * 128 + tid) : 0xffffffffu;
        unsigned cw = __reduce_min_sync(0xffffffffu, min(min(c[0], c[1]), min(c[2], c[3])));
        int sl = t & 1;
        if ((tid & 31) == 0) { cmb[w][sl] = mb; cix[w][sl] = cw; }
        __syncthreads();
        unsigned q0 = cmb[0][sl], q1 = cmb[1][sl], q2 = cmb[2][sl], q3 = cmb[3][sl];
        unsigned fm = max(max(q0, q1), max(q2, q3));
        unsigned i0 = (q0 == fm) ? cix[0][sl] : 0xffffffffu;
        unsigned i1 = (q1 == fm) ? cix[1][sl] : 0xffffffffu;
        unsigned i2 = (q2 == fm) ? cix[2][sl] : 0xffffffffu;
        unsigned i3 = (q3 == fm) ? cix[3][sl] : 0xffffffffu;
        far = (int)min(min(i0, i1), min(i2, i3));
        if (fm == 0u) {
            for (int q = t + 1 + tid; q < npoint; q += 128) out[q] = abs0;
            break;
        }
    }
}

// ---------------- launch ----------------
extern "C" void kernel_launch(void* const* d_in, const int* in_sizes, int n_in,
                              void* d_out, int out_size) {
    const float* x     = (const float*)d_in[0];
    const float* confW = (const float*)d_in[1];
    const float* confb = (const float*)d_in[2];
    const float* w1    = (const float*)d_in[3];
    const float* b1    = (const float*)d_in[4];
    const float* w2    = (const float*)d_in[5];
    const float* b2    = (const float*)d_in[6];
    const float* pc1W  = (const float*)d_in[7];
    const float* pc1b  = (const float*)d_in[8];
    const float* w3    = (const float*)d_in[9];
    const float* b3    = (const float*)d_in[10];
    const float* w4    = (const float*)d_in[11];
    const float* b4    = (const float*)d_in[12];
    const float* pc2W  = (const float*)d_in[13];
    const float* pc2b  = (const float*)d_in[14];
    const float* w5    = (const float*)d_in[15];
    const float* b5    = (const float*)d_in[16];
    const float* w6    = (const float*)d_in[17];
    const float* b6    = (const float*)d_in[18];
    const int* far1    = (const int*)d_in[20];
    const int* far2    = (const int*)d_in[21];
    float* out = (float*)d_out;

    __half *actP, *actQ, *wH, *tailX;
    int *idx1, *idx2;
    unsigned* maskp;
    cudaGetSymbolAddress((void**)&actP, g_actP);
    cudaGetSymbolAddress((void**)&actQ, g_actQ);
    cudaGetSymbolAddress((void**)&wH,   g_wH);
    cudaGetSymbolAddress((void**)&tailX, g_tailX);
    cudaGetSymbolAddress((void**)&idx1, g_idx1);
    cudaGetSymbolAddress((void**)&idx2, g_idx2);
    cudaGetSymbolAddress((void**)&maskp, g_mask);

    cudaFuncSetAttribute(gemm_f16, cudaFuncAttributeMaxDynamicSharedMemorySize, GEMM_SMEM);

    static cudaStream_t s1 = nullptr, s2 = nullptr;
    static cudaEvent_t evA = nullptr, ev1 = nullptr, ev2 = nullptr, evW = nullptr;
    if (s1 == nullptr) {
        cudaStreamCreateWithFlags(&s1, cudaStreamNonBlocking);
        cudaStreamCreateWithFlags(&s2, cudaStreamNonBlocking);
        cudaEventCreateWithFlags(&evA, cudaEventDisableTiming);
        cudaEventCreateWithFlags(&ev1, cudaEventDisableTiming);
        cudaEventCreateWithFlags(&ev2, cudaEventDisableTiming);
        cudaEventCreateWithFlags(&evW, cudaEventDisableTiming);
    }

    // fork: s1 = init_out + FPS1 ; s2 = init_mask + pack_w + FPS2 + mask
    cudaEventRecord(evA, 0);
    cudaStreamWaitEvent(s1, evA, 0);
    cudaStreamWaitEvent(s2, evA, 0);
    init_out<<<(BATCH * 512 + 255) / 256, 256, 0, s1>>>(out);
    fps_run<<<BATCH, 128, 0, s1>>>(x, far1, idx1, 500);
    cudaEventRecord(ev1, s1);
    init_mask<<<8, 256, 0, s2>>>();
    pack_w<<<(742400 + 255) / 256, 256, 0, s2>>>(w2, pc1W, w3, w4, pc2W, w5, w6);
    cudaEventRecord(evW, s2);
    fps_run<<<BATCH, 128, 0, s2>>>(x, far2, idx2, 1000);
    build_mask<<<(BATCH * 1000 + 255) / 256, 256, 0, s2>>>(idx2);
    cudaEventRecord(ev2, s2);

    // main stream: mlp1 (+tail fused), then GEMM chain (waits for weights)
    point_mlp1<<<(NROWS * 4 + 255) / 256, 256>>>(x, confW, confb, w1, b1);
    cudaStreamWaitEvent(0, evW, 0);

    // l2: (64000x256, K=64), relu        actP -> actQ
    gemm_f16<<<dim3(2, 500), 256, GEMM_SMEM>>>(actP, wH + OFF_W2, b2,
        nullptr, actQ, nullptr, nullptr, nullptr, NROWS, 256, 64, 64, 1, 1);
    // l3: (64000x256, K=256)             actQ -> actP
    gemm_f16<<<dim3(2, 500), 256, GEMM_SMEM>>>(actQ, wH + OFF_PC1, pc1b,
        nullptr, actP, nullptr, nullptr, nullptr, NROWS, 256, 256, 256, 0, 1);
    // l4' (natural order): A = l3 + x-tail, K=264, relu   actP -> actQ
    gemm_f16<<<dim3(2, 500), 256, GEMM_SMEM>>>(actP, wH + OFF_W3, b3,
        nullptr, actQ, nullptr, tailX, nullptr, NROWS, 256, 264, 256, 1, 1);
    // l5': (64000x384, K=256), relu      actQ -> actP
    gemm_f16<<<dim3(3, 500), 256, GEMM_SMEM>>>(actQ, wH + OFF_W4, b4,
        nullptr, actP, nullptr, nullptr, nullptr, NROWS, 384, 256, 256, 1, 1);
    // l6': (64000x384, K=384)            actP -> actQ
    gemm_f16<<<dim3(3, 500), 256, GEMM_SMEM>>>(actP, wH + OFF_PC2, pc2b,
        nullptr, actQ, nullptr, nullptr, nullptr, NROWS, 384, 384, 384, 0, 1);

    // join idx1; l7 over positions: A row j = l6'[idx1[j]], tail = x[j]
    cudaStreamWaitEvent(0, ev1, 0);
    gemm_f16<<<dim3(3, 500), 256, GEMM_SMEM>>>(actQ, wH + OFF_W5, b5,
        nullptr, actP, idx1, tailX, nullptr, NROWS, 384, 392, 384, 1, 1);

    // join idx2 bitmap; l8 masked fused max-pool -> out
    cudaStreamWaitEvent(0, ev2, 0);
    gemm_f16<<<dim3(4, 500), 256, GEMM_SMEM>>>(actP, wH + OFF_W6, b6,
        out, nullptr, nullptr, nullptr, maskp, NROWS, 512, 384, 384, 1, 2);
}

// round 16
// speedup vs baseline: 1.6506x; 1.6209x over previous
#include <cuda_runtime.h>
#include <cuda_fp16.h>
#include <math.h>
#include <cstdint>

#define BATCH 128
#define NPT   500
#define NROWS (BATCH*NPT)

typedef unsigned long long ull;

// ---------------- scratch (static; no allocation) ----------------
__device__ __align__(256) __half g_actP[52428800];
__device__ __align__(256) __half g_actQ[52428800];
__device__ __align__(256) __half g_wH[742528];
__device__ __align__(256) __half g_tailX[NROWS * 8];   // [x.xyz fp16, 0 x5] natural order
__device__ __align__(256) int g_idx1[BATCH * 500];
__device__ __align__(256) int g_idx2[BATCH * 1000];
__device__ __align__(256) unsigned g_mask[2048];       // 64000-bit idx2 membership bitmap

// weight arena offsets (elements, K padded to mult of 8)
#define OFF_W2   0
#define OFF_PC1  16384
#define OFF_W3   81920
#define OFF_W4   149504
#define OFF_PC2  247808
#define OFF_W5   395264
#define OFF_W6   545792

// ---------------- helpers ----------------
__device__ __forceinline__ uint32_t smem_u32(const void* p) {
    uint32_t a;
    asm("{ .reg .u64 t; cvta.to.shared.u64 t, %1; cvt.u32.u64 %0, t; }" : "=r"(a) : "l"(p));
    return a;
}
__device__ __forceinline__ void cpa16(uint32_t dst, const void* src, int sz) {
    asm volatile("cp.async.cg.shared.global [%0], [%1], 16, %2;"
        :: "r"(dst), "l"(src), "r"(sz) : "memory");
}
__device__ __forceinline__ void ldm_x4(uint32_t* r, uint32_t addr) {
    asm volatile("ldmatrix.sync.aligned.m8n8.x4.shared.b16 {%0,%1,%2,%3}, [%4];"
        : "=r"(r[0]), "=r"(r[1]), "=r"(r[2]), "=r"(r[3]) : "r"(addr));
}
__device__ __forceinline__ void mma_f16(float* d, const uint32_t* a, uint32_t b0, uint32_t b1) {
    asm volatile("mma.sync.aligned.m16n8k16.row.col.f32.f16.f16.f32 "
        "{%0,%1,%2,%3}, {%4,%5,%6,%7}, {%8,%9}, {%0,%1,%2,%3};"
        : "+f"(d[0]), "+f"(d[1]), "+f"(d[2]), "+f"(d[3])
        : "r"(a[0]), "r"(a[1]), "r"(a[2]), "r"(a[3]), "r"(b0), "r"(b1));
}

// ---------------- fp16 HMMA GEMM (R12-proven: CTA 128x128x64, 8 warps 2Mx4N, warp 64x32) ----
// C = relu?( sum_k A[m,k]*W[n,k] + bias[n] ). 3-stage cp.async (32KB/stage), 2 CTAs/SM.
// rowIdx: absolute A rows (smem-cached). tailA: K cols >= lda, indexed by OUTPUT row.
// mode: 0 fp32 C, 1 fp16 C, 2 fused masked per-500-row-batch column max into Cf.
#define NSTG 3
#define STG 32768
static const int GEMM_SMEM = NSTG * STG + 512;

__device__ __forceinline__ void g_fill(
    const __half* __restrict__ A, const __half* __restrict__ W,
    const int* __restrict__ sIdx, int useIdx, const __half* __restrict__ tailA,
    int K, int lda, int row0, int col0, int s, int nst, uint32_t sb, int tid)
{
    if (s < nst) {
        int k0 = s << 6;
        uint32_t base = sb + (uint32_t)(s % NSTG) * STG;
#pragma unroll
        for (int i = 0; i < 4; i++) {
            int g = (i << 8) + tid;
            int r = g >> 3, c = g & 7;
            int kg = k0 + (c << 3);
            int ok = (kg < K) ? 16 : 0;
            uint32_t d = base + ((uint32_t)r << 7) + (((uint32_t)(c ^ (r & 7))) << 4);
            int srcRow = useIdx ? sIdx[r] : (row0 + r);
            const __half* srcA;
            if (tailA != nullptr && kg >= lda)
                srcA = tailA + (size_t)(row0 + r) * 8 + (kg - lda);
            else
                srcA = A + (size_t)srcRow * lda + kg;
            cpa16(d,         srcA, ok);
            cpa16(d + 16384, W + (size_t)(col0 + r) * K + kg, ok);
        }
    }
    asm volatile("cp.async.commit_group;" ::: "memory");
}

__global__ void __launch_bounds__(256, 2)
gemm_f16(const __half* __restrict__ A, const __half* __restrict__ W,
         const float* __restrict__ bias,
         float* __restrict__ Cf, __half* __restrict__ Ch,
         const int* __restrict__ rowIdx, const __half* __restrict__ tailA,
         const unsigned* __restrict__ maskp,
         int M, int N, int K, int lda, int relu, int mode)
{
    extern __shared__ char smem[];
    int* sIdx = (int*)(smem + NSTG * STG);
    uint32_t sb = smem_u32(smem);
    int tid = threadIdx.x, lane = tid & 31, wid = tid >> 5;
    int warp_m = wid & 1;
    int warp_n = wid >> 1;
    int row0 = blockIdx.y << 7;
    int col0 = blockIdx.x << 7;
    int nst = (K + 63) >> 6;
    int useIdx = (rowIdx != nullptr);

    if (useIdx && tid < 128) sIdx[tid] = rowIdx[row0 + tid];
    __syncthreads();

    float acc[4][4][4];
#pragma unroll
    for (int a = 0; a < 4; a++)
#pragma unroll
        for (int b = 0; b < 4; b++)
#pragma unroll
            for (int c = 0; c < 4; c++) acc[a][b][c] = 0.f;

    g_fill(A, W, sIdx, useIdx, tailA, K, lda, row0, col0, 0, nst, sb, tid);
    g_fill(A, W, sIdx, useIdx, tailA, K, lda, row0, col0, 1, nst, sb, tid);

    int a_row = warp_m * 64 + (lane & 15);
    int a_sel = lane >> 4;
    int b_row4 = warp_n * 32 + ((lane >> 4) << 3) + (lane & 7);
    int b_ksel = (lane >> 3) & 1;

    for (int s = 0; s < nst; s++) {
        asm volatile("cp.async.wait_group 1;" ::: "memory");
        __syncthreads();
        uint32_t base = sb + (uint32_t)(s % NSTG) * STG;
        int kr = K - (s << 6);
        int kcnt = (kr + 15) >> 4; if (kcnt > 4) kcnt = 4;
        for (int ks = 0; ks < kcnt; ks++) {
            uint32_t Fa[4][4];
            int ch_a = (ks << 1) + a_sel;
#pragma unroll
            for (int mi = 0; mi < 4; mi++) {
                int rr = a_row + mi * 16;
                ldm_x4(Fa[mi], base + ((uint32_t)rr << 7) + (((uint32_t)(ch_a ^ (rr & 7))) << 4));
            }
            int ch_b = (ks << 1) + b_ksel;
#pragma unroll
            for (int np = 0; np < 2; np++) {
                int nr = b_row4 + np * 16;
                uint32_t B4[4];
                ldm_x4(B4, base + 16384 + ((uint32_t)nr << 7)
                           + (((uint32_t)(ch_b ^ (nr & 7))) << 4));
#pragma unroll
                for (int mi = 0; mi < 4; mi++) {
                    mma_f16(acc[mi][np * 2],     Fa[mi], B4[0], B4[1]);
                    mma_f16(acc[mi][np * 2 + 1], Fa[mi], B4[2], B4[3]);
                }
            }
        }
        g_fill(A, W, sIdx, useIdx, tailA, K, lda, row0, col0, s + 2, nst, sb, tid);
    }

    int er = row0 + warp_m * 64 + (lane >> 2);
    int ec = col0 + warp_n * 32 + ((lane & 3) << 1);
    if (mode != 2) {
#pragma unroll
        for (int ni = 0; ni < 4; ni++) {
            int c = ec + ni * 8;
            float b0 = __ldg(bias + c), b1 = __ldg(bias + c + 1);
#pragma unroll
            for (int mi = 0; mi < 4; mi++) {
                int r = er + mi * 16;
                float v00 = acc[mi][ni][0] + b0, v01 = acc[mi][ni][1] + b1;
                float v10 = acc[mi][ni][2] + b0, v11 = acc[mi][ni][3] + b1;
                if (relu) {
                    v00 = fmaxf(v00, 0.f); v01 = fmaxf(v01, 0.f);
                    v10 = fmaxf(v10, 0.f); v11 = fmaxf(v11, 0.f);
                }
                if (mode == 0) {
                    *(float2*)(Cf + (size_t)r * N + c)       = make_float2(v00, v01);
                    *(float2*)(Cf + (size_t)(r + 8) * N + c) = make_float2(v10, v11);
                } else {
                    *(__half2*)(Ch + (size_t)r * N + c)       = __floats2half2_rn(v00, v01);
                    *(__half2*)(Ch + (size_t)(r + 8) * N + c) = __floats2half2_rn(v10, v11);
                }
            }
        }
    } else {
        // masked per-batch (500 rows) column max -> Cf[batch][N] via atomicMax (values >= 0)
        int bat0 = row0 / 500;
        int cut = (bat0 + 1) * 500;
        bool has2 = (row0 + 127 >= cut);
        int* outI = (int*)Cf;
        float inc[8];
#pragma unroll
        for (int mi = 0; mi < 4; mi++) {
            int ra = er + mi * 16, rb = ra + 8;
            inc[mi * 2]     = ((maskp[ra >> 5] >> (ra & 31)) & 1u) ? 1.f : 0.f;
            inc[mi * 2 + 1] = ((maskp[rb >> 5] >> (rb & 31)) & 1u) ? 1.f : 0.f;
        }
#pragma unroll
        for (int ni = 0; ni < 4; ni++) {
            int c = ec + ni * 8;
            float b0 = __ldg(bias + c), b1 = __ldg(bias + c + 1);
            float s00 = 0.f, s01 = 0.f, s10 = 0.f, s11 = 0.f;
#pragma unroll
            for (int mi = 0; mi < 4; mi++) {
                int r = er + mi * 16;
                float v00 = fmaxf(acc[mi][ni][0] + b0, 0.f) * inc[mi * 2];
                float v01 = fmaxf(acc[mi][ni][1] + b1, 0.f) * inc[mi * 2];
                float v10 = fmaxf(acc[mi][ni][2] + b0, 0.f) * inc[mi * 2 + 1];
                float v11 = fmaxf(acc[mi][ni][3] + b1, 0.f) * inc[mi * 2 + 1];
                if (r < cut)     { s00 = fmaxf(s00, v00); s01 = fmaxf(s01, v01); }
                else             { s10 = fmaxf(s10, v00); s11 = fmaxf(s11, v01); }
                if (r + 8 < cut) { s00 = fmaxf(s00, v10); s01 = fmaxf(s01, v11); }
                else             { s10 = fmaxf(s10, v10); s11 = fmaxf(s11, v11); }
            }
#pragma unroll
            for (int d = 4; d <= 16; d <<= 1) {
                s00 = fmaxf(s00, __shfl_xor_sync(0xffffffffu, s00, d));
                s01 = fmaxf(s01, __shfl_xor_sync(0xffffffffu, s01, d));
                s10 = fmaxf(s10, __shfl_xor_sync(0xffffffffu, s10, d));
                s11 = fmaxf(s11, __shfl_xor_sync(0xffffffffu, s11, d));
            }
            if ((lane >> 2) == 0) {
                atomicMax(outI + bat0 * N + c,     __float_as_int(s00));
                atomicMax(outI + bat0 * N + c + 1, __float_as_int(s01));
                if (has2) {
                    atomicMax(outI + (bat0 + 1) * N + c,     __float_as_int(s10));
                    atomicMax(outI + (bat0 + 1) * N + c + 1, __float_as_int(s11));
                }
            }
        }
    }
}

// ---------------- out init ----------------
__global__ void init_out(float* __restrict__ out) {
    int t = blockIdx.x * 256 + threadIdx.x;
    if (t < BATCH * 512) out[t] = 0.f;
}

// ---------------- mask init + build ----------------
__global__ void init_mask() {
    int t = blockIdx.x * 256 + threadIdx.x;
    if (t < 2048) g_mask[t] = 0u;
}
__global__ void build_mask(const int* __restrict__ idx2) {
    int t = blockIdx.x * 256 + threadIdx.x;
    if (t >= BATCH * 1000) return;
    int v = idx2[t];
    atomicOr(&g_mask[v >> 5], 1u << (v & 31));
}

// ---------------- weight pack (fp32 -> fp16, pad K) ----------------
__global__ void pack_w(const float* __restrict__ w2, const float* __restrict__ pc1,
                       const float* __restrict__ w3, const float* __restrict__ w4,
                       const float* __restrict__ pc2, const float* __restrict__ w5,
                       const float* __restrict__ w6) {
    int t = blockIdx.x * 256 + threadIdx.x;
    if (t >= 742400) return;
    float v;
    if (t < 81920) {
        v = (t < 16384) ? w2[t] : pc1[t - 16384];
    } else if (t < 149504) {
        int i = t - 81920; int r = i / 264, c = i - r * 264;
        v = (c < 259) ? w3[r * 259 + c] : 0.f;
    } else if (t < 247808) {
        v = w4[t - 149504];
    } else if (t < 395264) {
        v = pc2[t - 247808];
    } else if (t < 545792) {
        int i = t - 395264; int r = i / 392, c = i - r * 392;
        v = (c < 387) ? w5[r * 387 + c] : 0.f;
    } else {
        v = w6[t - 545792];
    }
    g_wH[t] = __float2half_rn(v);
}

// ---------------- fused conf + concat + first linear + x-tail -> fp16 ----------------
__global__ void point_mlp1(const float* __restrict__ x,
                           const float* __restrict__ confW, const float* __restrict__ confb,
                           const float* __restrict__ w1, const float* __restrict__ b1) {
    int t = blockIdx.x * 256 + threadIdx.x;
    if (t >= NROWS * 4) return;
    int p = t >> 2, g = t & 3;
    float x0 = x[p * 3], x1 = x[p * 3 + 1], x2 = x[p * 3 + 2];
    float s = confW[0] * x0 + confW[1] * x1 + confW[2] * x2 + confb[0];
    float conf = 1.f / (1.f + expf(-s));
    const float* wr = w1 + (g * 16) * 4;
    __half h[16];
#pragma unroll
    for (int r = 0; r < 16; r++) {
        float a = __ldg(b1 + g * 16 + r)
                + __ldg(wr + r * 4 + 0) * conf + __ldg(wr + r * 4 + 1) * x0
                + __ldg(wr + r * 4 + 2) * x1   + __ldg(wr + r * 4 + 3) * x2;
        h[r] = __float2half_rn(fmaxf(a, 0.f));
    }
    size_t o = (size_t)p * 64 + g * 16;
    *(uint4*)(g_actP + o)     = *(uint4*)h;
    *(uint4*)(g_actP + o + 8) = *(uint4*)(h + 8);
    if (g == 0) {
        __half tx[8];
#pragma unroll
        for (int j = 0; j < 8; j++) tx[j] = __float2half(0.f);
        tx[0] = __float2half_rn(x0); tx[1] = __float2half_rn(x1); tx[2] = __float2half_rn(x2);
        *(uint4*)(g_tailX + (size_t)p * 8) = *(uint4*)tx;
    }
}

// ---------------- FPS: 4 warps/batch, exact XLA arithmetic, provable early-exit -------------
__global__ void fps_run(const float* __restrict__ x, const int* __restrict__ far0,
                        int* __restrict__ idxout, int npoint) {
    __shared__ float sxx[512], sxy[512], sxz[512];
    __shared__ unsigned cmb[4][2], cix[4][2];
    int b = blockIdx.x;
    int* out = idxout + b * npoint;
    int abs0 = b * NPT;
    int far = far0[b];
    const float* xb = x + (size_t)b * NPT * 3;
    int tid = threadIdx.x;
    int w = tid >> 5;

    float px[4], py[4], pz[4], dist[4];
#pragma unroll
    for (int j = 0; j < 4; j++) {
        int p = j * 128 + tid;
        if (p < NPT) {
            px[j] = xb[p * 3]; py[j] = xb[p * 3 + 1]; pz[j] = xb[p * 3 + 2];
            dist[j] = 1e10f;
            sxx[p] = px[j]; sxy[p] = py[j]; sxz[p] = pz[j];
        } else {
            px[j] = 0.f; py[j] = 0.f; pz[j] = 0.f;
            dist[j] = -1.0f;
        }
    }
    __syncthreads();

    for (int t = 0; t < npoint; t++) {
        if (tid == 0) out[t] = abs0 + far;
        if (t + 1 == npoint) break;
        float cx = sxx[far], cy = sxy[far], cz = sxz[far];
        float nd[4];
#pragma unroll
        for (int j = 0; j < 4; j++) {
            float dx = __fsub_rn(px[j], cx);
            float dy = __fsub_rn(py[j], cy);
            float dz = __fsub_rn(pz[j], cz);
            float d  = __fadd_rn(__fadd_rn(__fmul_rn(dx, dx), __fmul_rn(dy, dy)),
                                 __fmul_rn(dz, dz));
            nd[j] = fminf(dist[j], d);
            dist[j] = nd[j];
        }
        float m0 = fmaxf(nd[0], nd[1]), m1 = fmaxf(nd[2], nd[3]);
        float best = fmaxf(m0, m1);
        unsigned mb = __reduce_max_sync(0xffffffffu, __float_as_uint(best));
        unsigned c[4];
#pragma unroll
        for (int j = 0; j < 4; j++)
            c[j] = (__float_as_uint(nd[j]) == mb) ? (unsigned)(j * 128 + tid) : 0xffffffffu;
        unsigned cw = __reduce_min_sync(0xffffffffu, min(min(c[0], c[1]), min(c[2], c[3])));
        int sl = t & 1;
        if ((tid & 31) == 0) { cmb[w][sl] = mb; cix[w][sl] = cw; }
        __syncthreads();
        unsigned q0 = cmb[0][sl], q1 = cmb[1][sl], q2 = cmb[2][sl], q3 = cmb[3][sl];
        unsigned fm = max(max(q0, q1), max(q2, q3));
        unsigned i0 = (q0 == fm) ? cix[0][sl] : 0xffffffffu;
        unsigned i1 = (q1 == fm) ? cix[1][sl] : 0xffffffffu;
        unsigned i2 = (q2 == fm) ? cix[2][sl] : 0xffffffffu;
        unsigned i3 = (q3 == fm) ? cix[3][sl] : 0xffffffffu;
        far = (int)min(min(i0, i1), min(i2, i3));
        if (fm == 0u) {
            for (int q = t + 1 + tid; q < npoint; q += 128) out[q] = abs0;
            break;
        }
    }
}

// ---------------- launch (EXACT R12 structure; make_tailx fused into point_mlp1) ----------------
extern "C" void kernel_launch(void* const* d_in, const int* in_sizes, int n_in,
                              void* d_out, int out_size) {
    const float* x     = (const float*)d_in[0];
    const float* confW = (const float*)d_in[1];
    const float* confb = (const float*)d_in[2];
    const float* w1    = (const float*)d_in[3];
    const float* b1    = (const float*)d_in[4];
    const float* w2    = (const float*)d_in[5];
    const float* b2    = (const float*)d_in[6];
    const float* pc1W  = (const float*)d_in[7];
    const float* pc1b  = (const float*)d_in[8];
    const float* w3    = (const float*)d_in[9];
    const float* b3    = (const float*)d_in[10];
    const float* w4    = (const float*)d_in[11];
    const float* b4    = (const float*)d_in[12];
    const float* pc2W  = (const float*)d_in[13];
    const float* pc2b  = (const float*)d_in[14];
    const float* w5    = (const float*)d_in[15];
    const float* b5    = (const float*)d_in[16];
    const float* w6    = (const float*)d_in[17];
    const float* b6    = (const float*)d_in[18];
    const int* far1    = (const int*)d_in[20];
    const int* far2    = (const int*)d_in[21];
    float* out = (float*)d_out;

    __half *actP, *actQ, *wH, *tailX;
    int *idx1, *idx2;
    unsigned* maskp;
    cudaGetSymbolAddress((void**)&actP, g_actP);
    cudaGetSymbolAddress((void**)&actQ, g_actQ);
    cudaGetSymbolAddress((void**)&wH,   g_wH);
    cudaGetSymbolAddress((void**)&tailX, g_tailX);
    cudaGetSymbolAddress((void**)&idx1, g_idx1);
    cudaGetSymbolAddress((void**)&idx2, g_idx2);
    cudaGetSymbolAddress((void**)&maskp, g_mask);

    cudaFuncSetAttribute(gemm_f16, cudaFuncAttributeMaxDynamicSharedMemorySize, GEMM_SMEM);

    static cudaStream_t s1 = nullptr, s2 = nullptr;
    static cudaEvent_t evA = nullptr, ev1 = nullptr, ev2 = nullptr;
    if (s1 == nullptr) {
        cudaStreamCreateWithFlags(&s1, cudaStreamNonBlocking);
        cudaStreamCreateWithFlags(&s2, cudaStreamNonBlocking);
        cudaEventCreateWithFlags(&evA, cudaEventDisableTiming);
        cudaEventCreateWithFlags(&ev1, cudaEventDisableTiming);
        cudaEventCreateWithFlags(&ev2, cudaEventDisableTiming);
    }

    init_out<<<(BATCH * 512 + 255) / 256, 256>>>(out);

    // fork: FPS1 on s1; FPS2 + membership bitmap on s2  (R12 topology)
    cudaEventRecord(evA, 0);
    cudaStreamWaitEvent(s1, evA, 0);
    cudaStreamWaitEvent(s2, evA, 0);
    fps_run<<<BATCH, 128, 0, s1>>>(x, far1, idx1, 500);
    cudaEventRecord(ev1, s1);
    init_mask<<<8, 256, 0, s2>>>();
    fps_run<<<BATCH, 128, 0, s2>>>(x, far2, idx2, 1000);
    build_mask<<<(BATCH * 1000 + 255) / 256, 256, 0, s2>>>(idx2);
    cudaEventRecord(ev2, s2);

    // main stream head (as in R12): pack_w then point_mlp1 (tail fused)
    pack_w<<<(742400 + 255) / 256, 256>>>(w2, pc1W, w3, w4, pc2W, w5, w6);
    point_mlp1<<<(NROWS * 4 + 255) / 256, 256>>>(x, confW, confb, w1, b1);

    // l2: (64000x256, K=64), relu        actP -> actQ
    gemm_f16<<<dim3(2, 500), 256, GEMM_SMEM>>>(actP, wH + OFF_W2, b2,
        nullptr, actQ, nullptr, nullptr, nullptr, NROWS, 256, 64, 64, 1, 1);
    // l3: (64000x256, K=256)             actQ -> actP
    gemm_f16<<<dim3(2, 500), 256, GEMM_SMEM>>>(actQ, wH + OFF_PC1, pc1b,
        nullptr, actP, nullptr, nullptr, nullptr, NROWS, 256, 256, 256, 0, 1);
    // l4' (natural order): A = l3 + x-tail, K=264, relu   actP -> actQ
    gemm_f16<<<dim3(2, 500), 256, GEMM_SMEM>>>(actP, wH + OFF_W3, b3,
        nullptr, actQ, nullptr, tailX, nullptr, NROWS, 256, 264, 256, 1, 1);
    // l5': (64000x384, K=256), relu      actQ -> actP
    gemm_f16<<<dim3(3, 500), 256, GEMM_SMEM>>>(actQ, wH + OFF_W4, b4,
        nullptr, actP, nullptr, nullptr, nullptr, NROWS, 384, 256, 256, 1, 1);
    // l6': (64000x384, K=384)            actP -> actQ
    gemm_f16<<<dim3(3, 500), 256, GEMM_SMEM>>>(actP, wH + OFF_PC2, pc2b,
        nullptr, actQ, nullptr, nullptr, nullptr, NROWS, 384, 384, 384, 0, 1);

    // join idx1; l7 over positions: A row j = l6'[idx1[j]], tail = x[j]
    cudaStreamWaitEvent(0, ev1, 0);
    gemm_f16<<<dim3(3, 500), 256, GEMM_SMEM>>>(actQ, wH + OFF_W5, b5,
        nullptr, actP, idx1, tailX, nullptr, NROWS, 384, 392, 384, 1, 1);

    // join idx2 bitmap; l8 masked fused max-pool -> out
    cudaStreamWaitEvent(0, ev2, 0);
    gemm_f16<<<dim3(4, 500), 256, GEMM_SMEM>>>(actP, wH + OFF_W6, b6,
        out, nullptr, nullptr, nullptr, maskp, NROWS, 512, 384, 384, 1, 2);
}